// round 3
// baseline (speedup 1.0000x reference)
#include <cuda_runtime.h>
#include <cuda_fp16.h>
#include <cstdint>
#include <cstddef>

#define D_DIM   1024
#define NBATCH  16
#define NROWS   (NBATCH * D_DIM)

#define BM 128
#define BN 256
#define BK 64                 // fp16 per K-chunk = 128B row (SW128)
#define NSTG 3
#define NITER (D_DIM / BK)    // 16

#define A_TILE_BYTES (BM * 128)                    // 16 KB
#define B_TILE_BYTES (BN * 128)                    // 32 KB
#define STAGE_BYTES  (A_TILE_BYTES + B_TILE_BYTES) // 48 KB
#define SMEM_BYTES   (NSTG * STAGE_BYTES)          // 144 KB

// fp16 normalized-row scratch (allocation-free: __device__ globals)
__device__ __half g_ra[(size_t)NBATCH * D_DIM * D_DIM];
__device__ __half g_rb[(size_t)NBATCH * D_DIM * D_DIM];

// ---------------------------------------------------------------- helpers
static __device__ __forceinline__ uint32_t smem_u32(const void* p) {
    uint32_t a;
    asm("{ .reg .u64 t; cvta.to.shared.u64 t, %1; cvt.u32.u64 %0, t; }"
        : "=r"(a) : "l"(p));
    return a;
}
static __device__ __forceinline__ uint32_t sw128(uint32_t o) {
    return o ^ ((o >> 3) & 0x70u);
}
static __device__ __forceinline__ void cp16(uint32_t dst, const void* src) {
    asm volatile("cp.async.cg.shared.global [%0], [%1], 16;"
                 :: "r"(dst), "l"(src) : "memory");
}
static __device__ __forceinline__ void ldmatrix_x4(uint32_t* r, uint32_t addr) {
    asm volatile("ldmatrix.sync.aligned.m8n8.x4.shared.b16 {%0,%1,%2,%3}, [%4];"
                 : "=r"(r[0]), "=r"(r[1]), "=r"(r[2]), "=r"(r[3]) : "r"(addr));
}
static __device__ __forceinline__ void mma16816(float* d, const uint32_t* a,
                                                const uint32_t* b) {
    asm volatile(
        "mma.sync.aligned.m16n8k16.row.col.f32.f16.f16.f32 "
        "{%0,%1,%2,%3}, {%4,%5,%6,%7}, {%8,%9}, {%0,%1,%2,%3};"
        : "+f"(d[0]), "+f"(d[1]), "+f"(d[2]), "+f"(d[3])
        : "r"(a[0]), "r"(a[1]), "r"(a[2]), "r"(a[3]), "r"(b[0]), "r"(b[1]));
}

// ---------------------------------------------------------------- normalize
__global__ void __launch_bounds__(128) norm_kernel(const float* __restrict__ a,
                                                   const float* __restrict__ b,
                                                   const float* __restrict__ w) {
    const int row = blockIdx.x;
    const float* src = (blockIdx.y == 0) ? a : b;
    __half* dst = (blockIdx.y == 0) ? g_ra : g_rb;
    const int t = threadIdx.x;

    const float4* s4 = reinterpret_cast<const float4*>(src + (size_t)row * D_DIM);
    const float4* w4 = reinterpret_cast<const float4*>(w);

    float4 x0 = s4[t];       float4 w0 = w4[t];
    float4 x1 = s4[t + 128]; float4 w1 = w4[t + 128];
    float4 v0, v1;
    v0.x = x0.x * w0.x; v0.y = x0.y * w0.y; v0.z = x0.z * w0.z; v0.w = x0.w * w0.w;
    v1.x = x1.x * w1.x; v1.y = x1.y * w1.y; v1.z = x1.z * w1.z; v1.w = x1.w * w1.w;

    float sum = v0.x * v0.x + v0.y * v0.y + v0.z * v0.z + v0.w * v0.w
              + v1.x * v1.x + v1.y * v1.y + v1.z * v1.z + v1.w * v1.w;
#pragma unroll
    for (int o = 16; o > 0; o >>= 1) sum += __shfl_xor_sync(0xFFFFFFFFu, sum, o);

    __shared__ float red[4];
    if ((t & 31) == 0) red[t >> 5] = sum;
    __syncthreads();
    float tot = red[0] + red[1] + red[2] + red[3];
    float s = rsqrtf(fmaxf(tot, 1e-12f));

    __half2* d2 = reinterpret_cast<__half2*>(dst + (size_t)row * D_DIM);
    d2[2 * t + 0]         = __floats2half2_rn(v0.x * s, v0.y * s);
    d2[2 * t + 1]         = __floats2half2_rn(v0.z * s, v0.w * s);
    d2[2 * (t + 128) + 0] = __floats2half2_rn(v1.x * s, v1.y * s);
    d2[2 * (t + 128) + 1] = __floats2half2_rn(v1.z * s, v1.w * s);
}

// ---------------------------------------------------------------- GEMM
// C[b,i,j] = sum_k RA[b,i,k] * RB[b,j,k]; 128x256 block tile, 64x64 warp tile.
static __device__ __forceinline__ void load_stage(uint32_t stg,
                                                  const __half* gA, const __half* gB,
                                                  int kof, int tid) {
    // A: 1024 16B segments (128 rows x 8)
#pragma unroll
    for (int i = 0; i < 4; i++) {
        int q = i * 256 + tid;
        int row = q >> 3;
        int colb = (q & 7) * 16;
        cp16(stg + sw128((uint32_t)(row * 128 + colb)),
             (const char*)(gA + (size_t)row * D_DIM + kof) + colb);
    }
    // B: 2048 16B segments (256 rows x 8)
#pragma unroll
    for (int i = 0; i < 8; i++) {
        int q = i * 256 + tid;
        int row = q >> 3;
        int colb = (q & 7) * 16;
        cp16(stg + A_TILE_BYTES + sw128((uint32_t)(row * 128 + colb)),
             (const char*)(gB + (size_t)row * D_DIM + kof) + colb);
    }
    asm volatile("cp.async.commit_group;" ::: "memory");
}

__global__ void __launch_bounds__(256, 1) gemm_kernel(float* __restrict__ out) {
    extern __shared__ char smem[];
    const uint32_t sb = smem_u32(smem);
    const int tid  = threadIdx.x;
    const int wid  = tid >> 5;
    const int lane = tid & 31;
    const int wm   = wid & 1;        // 2 warps along M: 64 rows each
    const int wn   = wid >> 1;       // 4 warps along N: 64 cols each
    const int bn0   = blockIdx.x * BN;
    const int bm0   = blockIdx.y * BM;
    const int batch = blockIdx.z;

    const __half* gA = g_ra + (size_t)batch * (D_DIM * D_DIM) + (size_t)bm0 * D_DIM;
    const __half* gB = g_rb + (size_t)batch * (D_DIM * D_DIM) + (size_t)bn0 * D_DIM;

    float acc[4][8][4];
#pragma unroll
    for (int i = 0; i < 4; i++)
#pragma unroll
        for (int j = 0; j < 8; j++)
#pragma unroll
            for (int v = 0; v < 4; v++) acc[i][j][v] = 0.0f;

    // ldmatrix lane address components (within one 128B-row swizzled tile)
    const int aRow  = lane & 15;               // A x4
    const int aColb = (lane >> 4) << 4;
    const int bRow  = ((lane >> 4) << 3) + (lane & 7);  // B x4
    const int bColb = ((lane >> 3) & 1) << 4;

    // prologue: 2 stages in flight
    load_stage(sb + 0 * STAGE_BYTES, gA, gB, 0 * BK, tid);
    load_stage(sb + 1 * STAGE_BYTES, gA, gB, 1 * BK, tid);

    for (int it = 0; it < NITER; it++) {
        asm volatile("cp.async.wait_group 1;" ::: "memory");
        __syncthreads();
        // Safe to overwrite stage (it+2)%3 == (it-1)%3: its reads finished in
        // iteration it-1, and every warp has passed this barrier.
        if (it + 2 < NITER) {
            load_stage(sb + ((it + 2) % NSTG) * STAGE_BYTES, gA, gB, (it + 2) * BK, tid);
        } else {
            asm volatile("cp.async.commit_group;" ::: "memory");
        }

        const uint32_t aT = sb + (it % NSTG) * STAGE_BYTES;
        const uint32_t bT = aT + A_TILE_BYTES;

#pragma unroll
        for (int kk = 0; kk < 4; kk++) {       // 4 x k16 per BK=64
            const int kb = kk * 32;
            uint32_t af[4][4], bf[4][4];
#pragma unroll
            for (int mt = 0; mt < 4; mt++) {
                int row = wm * 64 + mt * 16 + aRow;
                ldmatrix_x4(af[mt], aT + sw128((uint32_t)(row * 128 + kb + aColb)));
            }
#pragma unroll
            for (int nq = 0; nq < 4; nq++) {   // each covers n16 (2 n8 tiles)
                int row = wn * 64 + nq * 16 + bRow;
                ldmatrix_x4(bf[nq], bT + sw128((uint32_t)(row * 128 + kb + bColb)));
            }
#pragma unroll
            for (int mt = 0; mt < 4; mt++)
#pragma unroll
                for (int nt = 0; nt < 8; nt++)
                    mma16816(acc[mt][nt], af[mt], &bf[nt >> 1][(nt & 1) * 2]);
        }
    }

    // epilogue: c0,c1 -> (m = lane>>2, n = (lane&3)*2); c2,c3 -> m+8
    float* oB = out + (size_t)batch * (D_DIM * D_DIM);
#pragma unroll
    for (int mt = 0; mt < 4; mt++) {
        int row = bm0 + wm * 64 + mt * 16 + (lane >> 2);
#pragma unroll
        for (int nt = 0; nt < 8; nt++) {
            int col = bn0 + wn * 64 + nt * 8 + (lane & 3) * 2;
            float2 lo = make_float2(acc[mt][nt][0], acc[mt][nt][1]);
            float2 hi = make_float2(acc[mt][nt][2], acc[mt][nt][3]);
            *reinterpret_cast<float2*>(oB + (size_t)row * D_DIM + col) = lo;
            *reinterpret_cast<float2*>(oB + (size_t)(row + 8) * D_DIM + col) = hi;
        }
    }
}

// ---------------------------------------------------------------- launch
extern "C" void kernel_launch(void* const* d_in, const int* in_sizes, int n_in,
                              void* d_out, int out_size) {
    const float* a = (const float*)d_in[0];
    const float* b = (const float*)d_in[1];
    const float* w = (const float*)d_in[2];
    float* out = (float*)d_out;

    norm_kernel<<<dim3(NROWS, 2, 1), 128>>>(a, b, w);

    cudaFuncSetAttribute(gemm_kernel, cudaFuncAttributeMaxDynamicSharedMemorySize,
                         SMEM_BYTES);
    gemm_kernel<<<dim3(D_DIM / BN, D_DIM / BM, NBATCH), 256, SMEM_BYTES>>>(out);
}

// round 5
// speedup vs baseline: 1.1040x; 1.1040x over previous
#include <cuda_runtime.h>
#include <cuda_fp16.h>
#include <cstdint>
#include <cstddef>

#define D_DIM   1024
#define NBATCH  16
#define NROWS   (NBATCH * D_DIM)

#define BM 128
#define BN 128
#define BK 64                 // fp16 per K-chunk = 128B row (SW128)
#define NSTG 3
#define NITER (D_DIM / BK)    // 16

#define TILE_BYTES  (BM * 128)           // 16 KB per operand per stage
#define STAGE_BYTES (2 * TILE_BYTES)     // 32 KB
#define SMEM_BYTES  (NSTG * STAGE_BYTES) // 96 KB

// fp16 normalized-row scratch (allocation-free: __device__ globals)
__device__ __half g_ra[(size_t)NBATCH * D_DIM * D_DIM];
__device__ __half g_rb[(size_t)NBATCH * D_DIM * D_DIM];

// ---------------------------------------------------------------- helpers
static __device__ __forceinline__ uint32_t smem_u32(const void* p) {
    uint32_t a;
    asm("{ .reg .u64 t; cvta.to.shared.u64 t, %1; cvt.u32.u64 %0, t; }"
        : "=r"(a) : "l"(p));
    return a;
}
static __device__ __forceinline__ uint32_t sw128(uint32_t o) {
    return o ^ ((o >> 3) & 0x70u);
}
static __device__ __forceinline__ void cp16(uint32_t dst, const void* src) {
    asm volatile("cp.async.cg.shared.global [%0], [%1], 16;"
                 :: "r"(dst), "l"(src) : "memory");
}
static __device__ __forceinline__ void ldmatrix_x4(uint32_t* r, uint32_t addr) {
    asm volatile("ldmatrix.sync.aligned.m8n8.x4.shared.b16 {%0,%1,%2,%3}, [%4];"
                 : "=r"(r[0]), "=r"(r[1]), "=r"(r[2]), "=r"(r[3]) : "r"(addr));
}
static __device__ __forceinline__ void mma16816(float* d, const uint32_t* a,
                                                const uint32_t* b) {
    asm volatile(
        "mma.sync.aligned.m16n8k16.row.col.f32.f16.f16.f32 "
        "{%0,%1,%2,%3}, {%4,%5,%6,%7}, {%8,%9}, {%0,%1,%2,%3};"
        : "+f"(d[0]), "+f"(d[1]), "+f"(d[2]), "+f"(d[3])
        : "r"(a[0]), "r"(a[1]), "r"(a[2]), "r"(a[3]), "r"(b[0]), "r"(b[1]));
}

// ---------------------------------------------------------------- normalize
__global__ void __launch_bounds__(128) norm_kernel(const float* __restrict__ a,
                                                   const float* __restrict__ b,
                                                   const float* __restrict__ w) {
    const int row = blockIdx.x;
    const float* src = (blockIdx.y == 0) ? a : b;
    __half* dst = (blockIdx.y == 0) ? g_ra : g_rb;
    const int t = threadIdx.x;

    const float4* s4 = reinterpret_cast<const float4*>(src + (size_t)row * D_DIM);
    const float4* w4 = reinterpret_cast<const float4*>(w);

    float4 x0 = s4[t];       float4 w0 = w4[t];
    float4 x1 = s4[t + 128]; float4 w1 = w4[t + 128];
    float4 v0, v1;
    v0.x = x0.x * w0.x; v0.y = x0.y * w0.y; v0.z = x0.z * w0.z; v0.w = x0.w * w0.w;
    v1.x = x1.x * w1.x; v1.y = x1.y * w1.y; v1.z = x1.z * w1.z; v1.w = x1.w * w1.w;

    float sum = v0.x * v0.x + v0.y * v0.y + v0.z * v0.z + v0.w * v0.w
              + v1.x * v1.x + v1.y * v1.y + v1.z * v1.z + v1.w * v1.w;
#pragma unroll
    for (int o = 16; o > 0; o >>= 1) sum += __shfl_xor_sync(0xFFFFFFFFu, sum, o);

    __shared__ float red[4];
    if ((t & 31) == 0) red[t >> 5] = sum;
    __syncthreads();
    float tot = red[0] + red[1] + red[2] + red[3];
    float s = rsqrtf(fmaxf(tot, 1e-12f));

    __half2* d2 = reinterpret_cast<__half2*>(dst + (size_t)row * D_DIM);
    d2[2 * t + 0]         = __floats2half2_rn(v0.x * s, v0.y * s);
    d2[2 * t + 1]         = __floats2half2_rn(v0.z * s, v0.w * s);
    d2[2 * (t + 128) + 0] = __floats2half2_rn(v1.x * s, v1.y * s);
    d2[2 * (t + 128) + 1] = __floats2half2_rn(v1.z * s, v1.w * s);
}

// ---------------------------------------------------------------- GEMM
// C[b,i,j] = sum_k RA[b,i,k] * RB[b,j,k]; 128x128 block tile, 32x64 warp tile.
static __device__ __forceinline__ void load_stage(uint32_t stg,
                                                  const __half* gA, const __half* gB,
                                                  int kof, int tid) {
#pragma unroll
    for (int i = 0; i < 4; i++) {
        int q = i * 256 + tid;      // 1024 16B segments per operand tile
        int row = q >> 3;           // 0..127
        int colb = (q & 7) * 16;
        uint32_t so = sw128((uint32_t)(row * 128 + colb));
        cp16(stg + so,              (const char*)(gA + (size_t)row * D_DIM + kof) + colb);
        cp16(stg + TILE_BYTES + so, (const char*)(gB + (size_t)row * D_DIM + kof) + colb);
    }
    asm volatile("cp.async.commit_group;" ::: "memory");
}

__global__ void __launch_bounds__(256, 2) gemm_kernel(float* __restrict__ out) {
    extern __shared__ char smem[];
    const uint32_t sb = smem_u32(smem);
    const int tid  = threadIdx.x;
    const int wid  = tid >> 5;
    const int lane = tid & 31;
    const int wm   = wid & 3;        // 4 warps along M: 32 rows each
    const int wn   = wid >> 2;       // 2 warps along N: 64 cols each
    const int bn0   = blockIdx.x * BN;
    const int bm0   = blockIdx.y * BM;
    const int batch = blockIdx.z;

    const __half* gA = g_ra + (size_t)batch * (D_DIM * D_DIM) + (size_t)bm0 * D_DIM;
    const __half* gB = g_rb + (size_t)batch * (D_DIM * D_DIM) + (size_t)bn0 * D_DIM;

    float acc[2][8][4];
#pragma unroll
    for (int i = 0; i < 2; i++)
#pragma unroll
        for (int j = 0; j < 8; j++)
#pragma unroll
            for (int v = 0; v < 4; v++) acc[i][j][v] = 0.0f;

    // Precomputed swizzled ldmatrix offsets (tile-relative).
    // Base x has zero bits at positions 5-6 (colb is bit 4 only), and
    // kb = kk*32 occupies bits 5-6 without affecting swizzle source bits
    // [9:7], so sw128(x + kb) == sw128(x) XOR kb. (Add is WRONG: sw128 may
    // set bits 5-6 and the add would carry into the row field.)
    const int aRow  = lane & 15;
    const int aColb = (lane >> 4) << 4;
    const int bRow  = ((lane >> 4) << 3) + (lane & 7);
    const int bColb = ((lane >> 3) & 1) << 4;

    uint32_t aOff[2], bOff[4];
#pragma unroll
    for (int mt = 0; mt < 2; mt++)
        aOff[mt] = sw128((uint32_t)((wm * 32 + mt * 16 + aRow) * 128 + aColb));
#pragma unroll
    for (int nq = 0; nq < 4; nq++)
        bOff[nq] = sw128((uint32_t)((wn * 64 + nq * 16 + bRow) * 128 + bColb))
                 + TILE_BYTES;

    // prologue: 2 stages in flight
    load_stage(sb + 0 * STAGE_BYTES, gA, gB, 0 * BK, tid);
    load_stage(sb + 1 * STAGE_BYTES, gA, gB, 1 * BK, tid);

    for (int it = 0; it < NITER; it++) {
        // Invariant: newest group before this wait is chunk it+1's (or an
        // empty tail group), so wait_group 1 => chunk it is fully resident.
        asm volatile("cp.async.wait_group 1;" ::: "memory");
        __syncthreads();
        // All warps finished reading stage (it+2)%3 == (it-1)%3 in iteration
        // it-1 before passing the barrier above: safe to overwrite now.
        if (it + 2 < NITER)
            load_stage(sb + ((it + 2) % NSTG) * STAGE_BYTES, gA, gB, (it + 2) * BK, tid);
        else
            asm volatile("cp.async.commit_group;" ::: "memory");

        const uint32_t sT = sb + (it % NSTG) * STAGE_BYTES;

#pragma unroll
        for (int kk = 0; kk < 4; kk++) {       // 4 x k16 per BK=64
            const uint32_t kb = kk * 32;
            uint32_t af[2][4], bf[4][4];
#pragma unroll
            for (int mt = 0; mt < 2; mt++)
                ldmatrix_x4(af[mt], sT + (aOff[mt] ^ kb));
#pragma unroll
            for (int nq = 0; nq < 4; nq++)
                ldmatrix_x4(bf[nq], sT + (bOff[nq] ^ kb));
#pragma unroll
            for (int mt = 0; mt < 2; mt++)
#pragma unroll
                for (int nt = 0; nt < 8; nt++)
                    mma16816(acc[mt][nt], af[mt], &bf[nt >> 1][(nt & 1) * 2]);
        }
    }

    // epilogue: c0,c1 -> (m = lane>>2, n = (lane&3)*2); c2,c3 -> m+8
    float* oB = out + (size_t)batch * (D_DIM * D_DIM);
#pragma unroll
    for (int mt = 0; mt < 2; mt++) {
        int row = bm0 + wm * 32 + mt * 16 + (lane >> 2);
#pragma unroll
        for (int nt = 0; nt < 8; nt++) {
            int col = bn0 + wn * 64 + nt * 8 + (lane & 3) * 2;
            float2 lo = make_float2(acc[mt][nt][0], acc[mt][nt][1]);
            float2 hi = make_float2(acc[mt][nt][2], acc[mt][nt][3]);
            *reinterpret_cast<float2*>(oB + (size_t)row * D_DIM + col) = lo;
            *reinterpret_cast<float2*>(oB + (size_t)(row + 8) * D_DIM + col) = hi;
        }
    }
}

// ---------------------------------------------------------------- launch
extern "C" void kernel_launch(void* const* d_in, const int* in_sizes, int n_in,
                              void* d_out, int out_size) {
    const float* a = (const float*)d_in[0];
    const float* b = (const float*)d_in[1];
    const float* w = (const float*)d_in[2];
    float* out = (float*)d_out;

    norm_kernel<<<dim3(NROWS, 2, 1), 128>>>(a, b, w);

    cudaFuncSetAttribute(gemm_kernel, cudaFuncAttributeMaxDynamicSharedMemorySize,
                         SMEM_BYTES);
    gemm_kernel<<<dim3(D_DIM / BN, D_DIM / BM, NBATCH), 256, SMEM_BYTES>>>(out);
}

// round 6
// speedup vs baseline: 1.1221x; 1.0164x over previous
#include <cuda_runtime.h>
#include <cuda_fp16.h>
#include <cstdint>
#include <cstddef>

#define D_DIM   1024
#define NBATCH  16
#define NROWS   (NBATCH * D_DIM)

#define BM 128
#define BN 128
#define BK 64                 // fp16 per K-chunk = 128B row (SW128)
#define NSTG 2
#define NITER (D_DIM / BK)    // 16

#define TILE_BYTES  (BM * 128)           // 16 KB per operand per stage
#define STAGE_BYTES (2 * TILE_BYTES)     // 32 KB
#define SMEM_BYTES  (NSTG * STAGE_BYTES) // 64 KB

// fp16 normalized-row scratch (allocation-free: __device__ globals)
__device__ __half g_ra[(size_t)NBATCH * D_DIM * D_DIM];
__device__ __half g_rb[(size_t)NBATCH * D_DIM * D_DIM];

// ---------------------------------------------------------------- helpers
static __device__ __forceinline__ uint32_t smem_u32(const void* p) {
    uint32_t a;
    asm("{ .reg .u64 t; cvta.to.shared.u64 t, %1; cvt.u32.u64 %0, t; }"
        : "=r"(a) : "l"(p));
    return a;
}
static __device__ __forceinline__ uint32_t sw128(uint32_t o) {
    return o ^ ((o >> 3) & 0x70u);
}
static __device__ __forceinline__ void cp16(uint32_t dst, const void* src) {
    asm volatile("cp.async.cg.shared.global [%0], [%1], 16;"
                 :: "r"(dst), "l"(src) : "memory");
}
static __device__ __forceinline__ void ldmatrix_x4(uint32_t* r, uint32_t addr) {
    asm volatile("ldmatrix.sync.aligned.m8n8.x4.shared.b16 {%0,%1,%2,%3}, [%4];"
                 : "=r"(r[0]), "=r"(r[1]), "=r"(r[2]), "=r"(r[3]) : "r"(addr));
}
static __device__ __forceinline__ void mma16816(float* d, const uint32_t* a,
                                                const uint32_t* b) {
    asm volatile(
        "mma.sync.aligned.m16n8k16.row.col.f32.f16.f16.f32 "
        "{%0,%1,%2,%3}, {%4,%5,%6,%7}, {%8,%9}, {%0,%1,%2,%3};"
        : "+f"(d[0]), "+f"(d[1]), "+f"(d[2]), "+f"(d[3])
        : "r"(a[0]), "r"(a[1]), "r"(a[2]), "r"(a[3]), "r"(b[0]), "r"(b[1]));
}

// ---------------------------------------------------------------- normalize
__global__ void __launch_bounds__(128) norm_kernel(const float* __restrict__ a,
                                                   const float* __restrict__ b,
                                                   const float* __restrict__ w) {
    const int row = blockIdx.x;
    const float* src = (blockIdx.y == 0) ? a : b;
    __half* dst = (blockIdx.y == 0) ? g_ra : g_rb;
    const int t = threadIdx.x;

    const float4* s4 = reinterpret_cast<const float4*>(src + (size_t)row * D_DIM);
    const float4* w4 = reinterpret_cast<const float4*>(w);

    float4 x0 = s4[t];       float4 w0 = w4[t];
    float4 x1 = s4[t + 128]; float4 w1 = w4[t + 128];
    float4 v0, v1;
    v0.x = x0.x * w0.x; v0.y = x0.y * w0.y; v0.z = x0.z * w0.z; v0.w = x0.w * w0.w;
    v1.x = x1.x * w1.x; v1.y = x1.y * w1.y; v1.z = x1.z * w1.z; v1.w = x1.w * w1.w;

    float sum = v0.x * v0.x + v0.y * v0.y + v0.z * v0.z + v0.w * v0.w
              + v1.x * v1.x + v1.y * v1.y + v1.z * v1.z + v1.w * v1.w;
#pragma unroll
    for (int o = 16; o > 0; o >>= 1) sum += __shfl_xor_sync(0xFFFFFFFFu, sum, o);

    __shared__ float red[4];
    if ((t & 31) == 0) red[t >> 5] = sum;
    __syncthreads();
    float tot = red[0] + red[1] + red[2] + red[3];
    float s = rsqrtf(fmaxf(tot, 1e-12f));

    __half2* d2 = reinterpret_cast<__half2*>(dst + (size_t)row * D_DIM);
    d2[2 * t + 0]         = __floats2half2_rn(v0.x * s, v0.y * s);
    d2[2 * t + 1]         = __floats2half2_rn(v0.z * s, v0.w * s);
    d2[2 * (t + 128) + 0] = __floats2half2_rn(v1.x * s, v1.y * s);
    d2[2 * (t + 128) + 1] = __floats2half2_rn(v1.z * s, v1.w * s);
}

// ---------------------------------------------------------------- GEMM
// 128x128 block tile, 4 warps, 64x64 warp tile, 2-stage cp.async ring,
// targeting 3 CTAs/SM (64 KB smem, <=170 regs).
static __device__ __forceinline__ void load_stage(uint32_t stg,
                                                  const __half* gA, const __half* gB,
                                                  int kof, int tid) {
#pragma unroll
    for (int i = 0; i < 8; i++) {
        int q = i * 128 + tid;      // 1024 16B segments per operand tile
        int row = q >> 3;           // 0..127
        int colb = (q & 7) * 16;
        uint32_t so = sw128((uint32_t)(row * 128 + colb));
        cp16(stg + so,              (const char*)(gA + (size_t)row * D_DIM + kof) + colb);
        cp16(stg + TILE_BYTES + so, (const char*)(gB + (size_t)row * D_DIM + kof) + colb);
    }
    asm volatile("cp.async.commit_group;" ::: "memory");
}

__global__ void __launch_bounds__(128, 3) gemm_kernel(float* __restrict__ out) {
    extern __shared__ char smem[];
    const uint32_t sb = smem_u32(smem);
    const int tid  = threadIdx.x;
    const int wid  = tid >> 5;
    const int lane = tid & 31;
    const int wm   = wid & 1;        // 2 warps along M: 64 rows each
    const int wn   = wid >> 1;       // 2 warps along N: 64 cols each
    const int bn0   = blockIdx.x * BN;
    const int bm0   = blockIdx.y * BM;
    const int batch = blockIdx.z;

    const __half* gA = g_ra + (size_t)batch * (D_DIM * D_DIM) + (size_t)bm0 * D_DIM;
    const __half* gB = g_rb + (size_t)batch * (D_DIM * D_DIM) + (size_t)bn0 * D_DIM;

    float acc[4][8][4];
#pragma unroll
    for (int i = 0; i < 4; i++)
#pragma unroll
        for (int j = 0; j < 8; j++)
#pragma unroll
            for (int v = 0; v < 4; v++) acc[i][j][v] = 0.0f;

    // Precomputed swizzled ldmatrix offsets. kb = kk*32 sits in bits 5-6,
    // which are zero in the unswizzled base, so sw128(base+kb) == sw128(base)^kb.
    const int aRow  = lane & 15;
    const int aColb = (lane >> 4) << 4;
    const int bRow  = ((lane >> 4) << 3) + (lane & 7);
    const int bColb = ((lane >> 3) & 1) << 4;

    uint32_t aOff[4], bOff[4];
#pragma unroll
    for (int mt = 0; mt < 4; mt++)
        aOff[mt] = sw128((uint32_t)((wm * 64 + mt * 16 + aRow) * 128 + aColb));
#pragma unroll
    for (int nq = 0; nq < 4; nq++)
        bOff[nq] = sw128((uint32_t)((wn * 64 + nq * 16 + bRow) * 128 + bColb))
                 + TILE_BYTES;

    // prologue: both stages in flight
    load_stage(sb + 0 * STAGE_BYTES, gA, gB, 0 * BK, tid);
    load_stage(sb + 1 * STAGE_BYTES, gA, gB, 1 * BK, tid);

    for (int it = 0; it < NITER; it++) {
        // Newest committed group is chunk it+1's (or empty tail), so
        // wait_group 1 guarantees chunk it is fully resident.
        asm volatile("cp.async.wait_group 1;" ::: "memory");
        __syncthreads();

        const uint32_t sT = sb + (it & 1) * STAGE_BYTES;

#pragma unroll
        for (int kk = 0; kk < 4; kk++) {       // 4 x k16 per BK=64
            const uint32_t kb = kk * 32;
            uint32_t af[4][4];
#pragma unroll
            for (int mt = 0; mt < 4; mt++)
                ldmatrix_x4(af[mt], sT + (aOff[mt] ^ kb));
#pragma unroll
            for (int nq = 0; nq < 4; nq++) {
                uint32_t bf[4];
                ldmatrix_x4(bf, sT + (bOff[nq] ^ kb));
#pragma unroll
                for (int mt = 0; mt < 4; mt++) {
                    mma16816(acc[mt][2 * nq + 0], af[mt], bf + 0);
                    mma16816(acc[mt][2 * nq + 1], af[mt], bf + 2);
                }
            }
        }

        __syncthreads();   // all warps done reading stage it&1
        if (it + 2 < NITER)
            load_stage(sT, gA, gB, (it + 2) * BK, tid);
        else
            asm volatile("cp.async.commit_group;" ::: "memory");
    }

    // epilogue: c0,c1 -> (m = lane>>2, n = (lane&3)*2); c2,c3 -> m+8
    float* oB = out + (size_t)batch * (D_DIM * D_DIM);
#pragma unroll
    for (int mt = 0; mt < 4; mt++) {
        int row = bm0 + wm * 64 + mt * 16 + (lane >> 2);
#pragma unroll
        for (int nt = 0; nt < 8; nt++) {
            int col = bn0 + wn * 64 + nt * 8 + (lane & 3) * 2;
            float2 lo = make_float2(acc[mt][nt][0], acc[mt][nt][1]);
            float2 hi = make_float2(acc[mt][nt][2], acc[mt][nt][3]);
            *reinterpret_cast<float2*>(oB + (size_t)row * D_DIM + col) = lo;
            *reinterpret_cast<float2*>(oB + (size_t)(row + 8) * D_DIM + col) = hi;
        }
    }
}

// ---------------------------------------------------------------- launch
extern "C" void kernel_launch(void* const* d_in, const int* in_sizes, int n_in,
                              void* d_out, int out_size) {
    const float* a = (const float*)d_in[0];
    const float* b = (const float*)d_in[1];
    const float* w = (const float*)d_in[2];
    float* out = (float*)d_out;

    norm_kernel<<<dim3(NROWS, 2, 1), 128>>>(a, b, w);

    cudaFuncSetAttribute(gemm_kernel, cudaFuncAttributeMaxDynamicSharedMemorySize,
                         SMEM_BYTES);
    gemm_kernel<<<dim3(D_DIM / BN, D_DIM / BM, NBATCH), 128, SMEM_BYTES>>>(out);
}